// round 1
// baseline (speedup 1.0000x reference)
#include <cuda_runtime.h>
#include <math.h>

// ---------------------------------------------------------------------------
// img_attention: Bahdanau image attention
//   g1     = gf @ Wg + bg                [M, 4096]   M = b*t_k = 6272
//   g_star = g1 @ Gs + bgs               [M, 1024]
//   wgs    = g_star @ Wgs                [M, 1024]
//   dec    = s_t_hat @ Wdec + bdec       [b, 1024]
//   scores = tanh(wgs + dec[b] + cov) @ v  [M]
//   alpha  = softmax over t (per b)
//   c_img  = sum_t alpha * g_star        [b, 1024]
//   cov'   = cov + alpha
// Output layout: [c_img (b*DH) | coverage_new (b*T) | alpha (b*T)]
// ---------------------------------------------------------------------------

#define BM 128
#define BN 128
#define BK 8
#define TM 8
#define TN 8

// Scratch (allocation-free rule: __device__ globals)
__device__ float g_G1[6272u * 4096u];     // 102.8 MB
__device__ float g_Gstar[6272u * 1024u];  // 25.7 MB
__device__ float g_Wgstar[6272u * 1024u]; // 25.7 MB
__device__ float g_dec[32u * 1024u];
__device__ float g_scores[6272];
__device__ float g_alpha[6272];

// Classic tiled SGEMM: C[M,N] = A[M,K] @ B[K,N] (+ bias). A,B,C row-major.
// Requires N % 128 == 0, K % 8 == 0. M is bounds-checked.
__global__ __launch_bounds__(256, 2)
void sgemm_bias(const float* __restrict__ A, const float* __restrict__ B,
                const float* __restrict__ bias, float* __restrict__ C,
                int M, int N, int K)
{
    __shared__ float As[BK][BM];
    __shared__ float Bs[BK][BN];
    const int tid  = threadIdx.x;
    const int brow = blockIdx.y * BM;
    const int bcol = blockIdx.x * BN;

    const int tx = tid & 15;        // 16x16 thread grid
    const int ty = tid >> 4;
    const int row0 = ty * TM;
    const int col0 = tx * TN;

    // A tile loads: 128 rows x 8 cols = 256 float4 (one per thread)
    const int a_row = tid >> 1;
    const int a_c4  = (tid & 1) * 4;
    // B tile loads: 8 rows x 128 cols = 256 float4 (one per thread)
    const int b_row = tid >> 5;
    const int b_c4  = (tid & 31) * 4;

    float acc[TM][TN];
#pragma unroll
    for (int i = 0; i < TM; i++)
#pragma unroll
        for (int j = 0; j < TN; j++) acc[i][j] = 0.0f;

    const int garow = brow + a_row;
    const bool a_ok = (garow < M);
    const float* Aptr = A + (size_t)garow * K + a_c4;
    const float* Bptr = B + (size_t)b_row * N + bcol + b_c4;

    for (int k0 = 0; k0 < K; k0 += BK) {
        float4 av = make_float4(0.f, 0.f, 0.f, 0.f);
        if (a_ok) av = *(const float4*)(Aptr + k0);
        As[a_c4 + 0][a_row] = av.x;
        As[a_c4 + 1][a_row] = av.y;
        As[a_c4 + 2][a_row] = av.z;
        As[a_c4 + 3][a_row] = av.w;

        float4 bv = *(const float4*)(Bptr + (size_t)k0 * N);
        *(float4*)&Bs[b_row][b_c4] = bv;
        __syncthreads();

#pragma unroll
        for (int k = 0; k < BK; k++) {
            float ar[TM], br[TN];
#pragma unroll
            for (int i = 0; i < TM; i++) ar[i] = As[k][row0 + i];
#pragma unroll
            for (int j = 0; j < TN; j++) br[j] = Bs[k][col0 + j];
#pragma unroll
            for (int i = 0; i < TM; i++)
#pragma unroll
                for (int j = 0; j < TN; j++)
                    acc[i][j] = fmaf(ar[i], br[j], acc[i][j]);
        }
        __syncthreads();
    }

#pragma unroll
    for (int i = 0; i < TM; i++) {
        int gr = brow + row0 + i;
        if (gr >= M) continue;
#pragma unroll
        for (int j = 0; j < TN; j += 4) {
            int gc = bcol + col0 + j;
            float4 o;
            o.x = acc[i][j + 0];
            o.y = acc[i][j + 1];
            o.z = acc[i][j + 2];
            o.w = acc[i][j + 3];
            if (bias) {
                o.x += bias[gc + 0];
                o.y += bias[gc + 1];
                o.z += bias[gc + 2];
                o.w += bias[gc + 3];
            }
            *(float4*)&C[(size_t)gr * N + gc] = o;
        }
    }
}

// scores[bt] = sum_d tanh(wgs[bt,d] + dec[b,d] + cov[bt]) * v[d]
__global__ void scores_kernel(const float* __restrict__ Wgstar,
                              const float* __restrict__ dec,
                              const float* __restrict__ cov,
                              const float* __restrict__ v,
                              float* __restrict__ scores, int T, int DH)
{
    const int bt = blockIdx.x;
    const int b  = bt / T;
    const float c = cov[bt];
    const float* wrow = Wgstar + (size_t)bt * DH;
    const float* drow = dec + (size_t)b * DH;

    float s = 0.0f;
    for (int d = threadIdx.x; d < DH; d += blockDim.x)
        s += tanhf(wrow[d] + drow[d] + c) * v[d];

    __shared__ float red[256];
    red[threadIdx.x] = s;
    __syncthreads();
    for (int off = 128; off > 0; off >>= 1) {
        if (threadIdx.x < off) red[threadIdx.x] += red[threadIdx.x + off];
        __syncthreads();
    }
    if (threadIdx.x == 0) scores[bt] = red[0];
}

// Softmax over T per batch; also emits coverage_new and alpha outputs.
__global__ void softmax_kernel(const float* __restrict__ scores,
                               const float* __restrict__ cov,
                               float* __restrict__ alpha,
                               float* __restrict__ out_cov,
                               float* __restrict__ out_alpha, int T)
{
    const int b = blockIdx.x;
    const int tid = threadIdx.x;
    __shared__ float red[256];

    float m = -1e30f;
    for (int t = tid; t < T; t += blockDim.x) m = fmaxf(m, scores[b * T + t]);
    red[tid] = m;
    __syncthreads();
    for (int off = 128; off > 0; off >>= 1) {
        if (tid < off) red[tid] = fmaxf(red[tid], red[tid + off]);
        __syncthreads();
    }
    m = red[0];
    __syncthreads();

    float s = 0.0f;
    for (int t = tid; t < T; t += blockDim.x) s += expf(scores[b * T + t] - m);
    red[tid] = s;
    __syncthreads();
    for (int off = 128; off > 0; off >>= 1) {
        if (tid < off) red[tid] += red[tid + off];
        __syncthreads();
    }
    s = red[0];

    const float inv = 1.0f / s;
    for (int t = tid; t < T; t += blockDim.x) {
        float a = expf(scores[b * T + t] - m) * inv;
        alpha[b * T + t]     = a;
        out_alpha[b * T + t] = a;
        out_cov[b * T + t]   = cov[b * T + t] + a;
    }
}

// c[b,d] = sum_t alpha[b,t] * g_star[b,t,d]
__global__ void context_kernel(const float* __restrict__ alpha,
                               const float* __restrict__ Gstar,
                               float* __restrict__ out_c, int T, int DH)
{
    const int b = blockIdx.x;
    __shared__ float a_s[512];
    for (int t = threadIdx.x; t < T; t += blockDim.x) a_s[t] = alpha[b * T + t];
    __syncthreads();

    const float* gbase = Gstar + (size_t)b * T * DH;
    for (int d = threadIdx.x; d < DH; d += blockDim.x) {
        float acc = 0.0f;
        for (int t = 0; t < T; t++)
            acc = fmaf(a_s[t], gbase[(size_t)t * DH + d], acc);
        out_c[(size_t)b * DH + d] = acc;
    }
}

extern "C" void kernel_launch(void* const* d_in, const int* in_sizes, int n_in,
                              void* d_out, int out_size)
{
    const float* gf   = (const float*)d_in[0];   // [b, T, GFD]
    const float* sth  = (const float*)d_in[1];   // [b, DH]
    const float* cov  = (const float*)d_in[2];   // [b, T, 1]
    const float* Wg   = (const float*)d_in[3];   // [GFD, GFD]
    const float* bg   = (const float*)d_in[4];   // [GFD]
    const float* Gs   = (const float*)d_in[5];   // [GFD, DH]
    const float* bgs  = (const float*)d_in[6];   // [DH]
    const float* Wgs  = (const float*)d_in[7];   // [DH, DH]
    const float* Wdec = (const float*)d_in[8];   // [DH, DH]
    const float* bdec = (const float*)d_in[9];   // [DH]
    const float* v    = (const float*)d_in[10];  // [DH, 1]

    const int GFD = in_sizes[4];            // 4096
    const int DH  = in_sizes[9];            // 1024
    const int b   = in_sizes[1] / DH;       // 32
    const int T   = in_sizes[2] / b;        // 196
    const int M   = b * T;                  // 6272

    float *G1, *Gstar, *Wgstar, *dec, *scores, *alpha;
    cudaGetSymbolAddress((void**)&G1,     g_G1);
    cudaGetSymbolAddress((void**)&Gstar,  g_Gstar);
    cudaGetSymbolAddress((void**)&Wgstar, g_Wgstar);
    cudaGetSymbolAddress((void**)&dec,    g_dec);
    cudaGetSymbolAddress((void**)&scores, g_scores);
    cudaGetSymbolAddress((void**)&alpha,  g_alpha);

    dim3 blk(256);

    // GEMM1: g1 = gf @ Wg + bg        [M, GFD]
    sgemm_bias<<<dim3(GFD / BN, (M + BM - 1) / BM), blk>>>(gf, Wg, bg, G1, M, GFD, GFD);
    // GEMM2: g_star = g1 @ Gs + bgs   [M, DH]
    sgemm_bias<<<dim3(DH / BN, (M + BM - 1) / BM), blk>>>(G1, Gs, bgs, Gstar, M, DH, GFD);
    // GEMM3: wgs = g_star @ Wgs       [M, DH]
    sgemm_bias<<<dim3(DH / BN, (M + BM - 1) / BM), blk>>>(Gstar, Wgs, nullptr, Wgstar, M, DH, DH);
    // GEMM4: dec = s_t_hat @ Wdec + bdec   [b, DH]
    sgemm_bias<<<dim3(DH / BN, (b + BM - 1) / BM), blk>>>(sth, Wdec, bdec, dec, b, DH, DH);

    // scores + softmax + context + outputs
    scores_kernel<<<M, 256>>>(Wgstar, dec, cov, v, scores, T, DH);

    float* out_c     = (float*)d_out;                 // [b, DH]
    float* out_cov   = out_c + (size_t)b * DH;        // [b, T]
    float* out_alpha = out_cov + (size_t)b * T;       // [b, T]

    softmax_kernel<<<b, 256>>>(scores, cov, alpha, out_cov, out_alpha, T);
    context_kernel<<<b, 256>>>(alpha, Gstar, out_c, T, DH);
}

// round 5
// speedup vs baseline: 6.8556x; 6.8556x over previous
#include <cuda_runtime.h>
#include <cuda_bf16.h>
#include <cstdint>
#include <math.h>

// ---------------------------------------------------------------------------
// img_attention, mma.sync (HMMA) split-bf16 path, fused-weight algebra:
//   WfT    = (Wg @ Gs)^T            [1024, 4096]   (34.4 GF)
//   bfused = bg @ Gs + bgs          [1024]
//   g_star = gf @ Wf + bfused       [M, 1024]      (52.6 GF)
//   wgs    = g_star @ Wgs           [M, 1024]      (13.2 GF)
//   dec    = s_t_hat @ Wdec + bdec  [32, 1024]
//   scores = tanh(wgs + dec + cov) @ v; alpha = softmax_T; c = alpha @ g_star
// Output: [c_img (b*DH) | coverage_new (b*T) | alpha (b*T)]
// ---------------------------------------------------------------------------

// ---- scratch (__device__ globals; allocation-free rule) ----
__device__ __align__(1024) __nv_bfloat16 g_gf_hi[25690112];
__device__ __align__(1024) __nv_bfloat16 g_gf_lo[25690112];
__device__ __align__(1024) __nv_bfloat16 g_Wg_hi[16777216];
__device__ __align__(1024) __nv_bfloat16 g_Wg_lo[16777216];
__device__ __align__(1024) __nv_bfloat16 g_GsT_hi[4194304];
__device__ __align__(1024) __nv_bfloat16 g_GsT_lo[4194304];
__device__ __align__(1024) __nv_bfloat16 g_WfT_hi[4194304];
__device__ __align__(1024) __nv_bfloat16 g_WfT_lo[4194304];
__device__ __align__(1024) __nv_bfloat16 g_WgsT_hi[1048576];
__device__ __align__(1024) __nv_bfloat16 g_WgsT_lo[1048576];
__device__ __align__(1024) float g_Gstar[6422528];
__device__ __align__(1024) __nv_bfloat16 g_Gstar_hi[6422528];
__device__ __align__(1024) __nv_bfloat16 g_Gstar_lo[6422528];
__device__ __align__(1024) float g_Wgstar[6422528];
__device__ __align__(1024) float g_bfused[1024];
__device__ __align__(1024) float g_dec[32768];
__device__ __align__(1024) float g_scores[6272];
__device__ __align__(1024) float g_alpha[6272];

// ---------------------------------------------------------------------------
// helpers
// ---------------------------------------------------------------------------
__device__ __forceinline__ uint32_t smem_u32(const void* p) {
    uint32_t a;
    asm("{ .reg .u64 t; cvta.to.shared.u64 t, %1; cvt.u32.u64 %0, t; }" : "=r"(a) : "l"(p));
    return a;
}
__device__ __forceinline__ void cp16(uint32_t s, const void* g) {
    asm volatile("cp.async.cg.shared.global [%0], [%1], 16;" :: "r"(s), "l"(g));
}
__device__ __forceinline__ void ldsm4(uint32_t* r, uint32_t a) {
    asm volatile("ldmatrix.sync.aligned.m8n8.x4.shared.b16 {%0,%1,%2,%3}, [%4];"
                 : "=r"(r[0]), "=r"(r[1]), "=r"(r[2]), "=r"(r[3]) : "r"(a));
}
__device__ __forceinline__ void mma16816(float* d, const uint32_t* a, const uint32_t* b) {
    asm volatile(
        "mma.sync.aligned.m16n8k16.row.col.f32.bf16.bf16.f32 "
        "{%0,%1,%2,%3}, {%4,%5,%6,%7}, {%8,%9}, {%0,%1,%2,%3};"
        : "+f"(d[0]), "+f"(d[1]), "+f"(d[2]), "+f"(d[3])
        : "r"(a[0]), "r"(a[1]), "r"(a[2]), "r"(a[3]), "r"(b[0]), "r"(b[1]));
}
__device__ __forceinline__ uint32_t pack_bf2(float x, float y) {
    __nv_bfloat162 h = __floats2bfloat162_rn(x, y);
    return *(uint32_t*)&h;
}
__device__ __forceinline__ float tanh_fast(float x) {
    float e = __expf(2.0f * x);
    return 1.0f - __fdividef(2.0f, e + 1.0f);
}

// ---------------------------------------------------------------------------
// HMMA GEMM: C[M,N] = A[M,K] @ B^T (B stored [N,K]), split-bf16 3xMMA.
// BM=BN=128, BK=64, 3-stage cp.async, 8 warps (2m x 4n), warp tile 64x32.
// M,N multiples of 128; K multiple of 64.
// ---------------------------------------------------------------------------
#define BKT 64
#define OP_BYTES (128 * 64 * 2)          // 16 KB per operand tile
#define STG_BYTES (4 * OP_BYTES)         // 64 KB per stage
#define GEMM_SMEM (3 * STG_BYTES)        // 192 KB

__device__ __forceinline__ void load_stage(uint32_t stg,
    const __nv_bfloat16* __restrict__ Ah, const __nv_bfloat16* __restrict__ Al,
    const __nv_bfloat16* __restrict__ Bh, const __nv_bfloat16* __restrict__ Bl,
    int brow, int bcol, int K, int k0, int tid)
{
#pragma unroll
    for (int op = 0; op < 4; op++) {
        const __nv_bfloat16* P = (op == 0) ? Ah : (op == 1) ? Al : (op == 2) ? Bh : Bl;
        const int row0 = (op < 2) ? brow : bcol;
#pragma unroll
        for (int it = 0; it < 4; it++) {
            int idx = tid + it * 256;        // 0..1023
            int r = idx >> 3, c = idx & 7;
            uint32_t dst = stg + op * OP_BYTES + r * 128 + (((uint32_t)(c ^ (r & 7))) << 4);
            cp16(dst, P + (size_t)(row0 + r) * K + k0 + c * 8);
        }
    }
}

__global__ __launch_bounds__(256, 1)
void tc_gemm(const __nv_bfloat16* __restrict__ Ahi, const __nv_bfloat16* __restrict__ Alo,
             const __nv_bfloat16* __restrict__ Bhi, const __nv_bfloat16* __restrict__ Blo,
             const float* __restrict__ bias,
             float* __restrict__ Cf, __nv_bfloat16* __restrict__ Chi,
             __nv_bfloat16* __restrict__ Clo,
             int M, int N, int K)
{
    extern __shared__ __align__(128) char smem[];
    const uint32_t sbase = smem_u32(smem);
    const int tid = threadIdx.x, wid = tid >> 5, lane = tid & 31;
    const int wm = wid >> 2, wn = wid & 3;          // 2 x 4 warp grid
    const int brow = blockIdx.y * 128, bcol = blockIdx.x * 128;
    const int KT = K / BKT;

    // per-lane ldmatrix geometry (constant across k-tiles)
    const int rowA = wm * 64 + (lane & 15);
    const int phA  = rowA & 7;
    const int hiA  = lane >> 4;
    const int rowB = wn * 32 + ((lane >> 4) << 3) + (lane & 7);
    const int phB  = lane & 7;
    const int hiB  = (lane >> 3) & 1;

    float acc[4][4][4];
#pragma unroll
    for (int mt = 0; mt < 4; mt++)
#pragma unroll
        for (int nt = 0; nt < 4; nt++)
#pragma unroll
            for (int j = 0; j < 4; j++) acc[mt][nt][j] = 0.0f;

    // prologue: prefetch k-tiles 0, 1
    load_stage(sbase, Ahi, Alo, Bhi, Blo, brow, bcol, K, 0, tid);
    asm volatile("cp.async.commit_group;" ::: "memory");
    if (KT > 1) {
        load_stage(sbase + STG_BYTES, Ahi, Alo, Bhi, Blo, brow, bcol, K, BKT, tid);
        asm volatile("cp.async.commit_group;" ::: "memory");
    }

    for (int kt = 0; kt < KT; kt++) {
        // groups pending at this point: tiles kt and kt+1. Tile kt must be
        // complete before we read it -> allow at most 1 pending group.
        if (kt + 1 < KT) asm volatile("cp.async.wait_group 1;" ::: "memory");
        else             asm volatile("cp.async.wait_group 0;" ::: "memory");
        __syncthreads();

        const uint32_t stg = sbase + (kt % 3) * STG_BYTES;
        const uint32_t aH = stg, aL = stg + OP_BYTES;
        const uint32_t bH = stg + 2 * OP_BYTES, bL = stg + 3 * OP_BYTES;

#pragma unroll
        for (int ks = 0; ks < 4; ks++) {
            uint32_t ah[4][4], al[4][4], bh[2][4], bl[2][4];
            const uint32_t cA = ((uint32_t)((ks * 2 + hiA) ^ phA)) << 4;
            const uint32_t cB = ((uint32_t)((ks * 2 + hiB) ^ phB)) << 4;
#pragma unroll
            for (int mt = 0; mt < 4; mt++) {
                uint32_t ro = (uint32_t)(rowA + mt * 16) * 128 + cA;
                ldsm4(ah[mt], aH + ro);
                ldsm4(al[mt], aL + ro);
            }
#pragma unroll
            for (int p = 0; p < 2; p++) {
                uint32_t ro = (uint32_t)(rowB + p * 16) * 128 + cB;
                ldsm4(bh[p], bH + ro);
                ldsm4(bl[p], bL + ro);
            }
#pragma unroll
            for (int mt = 0; mt < 4; mt++)
#pragma unroll
                for (int nt = 0; nt < 4; nt++) {
                    float* d = acc[mt][nt];
                    const uint32_t* bhf = &bh[nt >> 1][(nt & 1) * 2];
                    const uint32_t* blf = &bl[nt >> 1][(nt & 1) * 2];
                    mma16816(d, ah[mt], bhf);
                    mma16816(d, ah[mt], blf);
                    mma16816(d, al[mt], bhf);
                }
        }

        if (kt + 2 < KT) {
            load_stage(sbase + ((kt + 2) % 3) * STG_BYTES,
                       Ahi, Alo, Bhi, Blo, brow, bcol, K, (kt + 2) * BKT, tid);
            asm volatile("cp.async.commit_group;" ::: "memory");
        }
    }

    // epilogue
#pragma unroll
    for (int mt = 0; mt < 4; mt++)
#pragma unroll
        for (int nt = 0; nt < 4; nt++) {
            const int r0 = brow + wm * 64 + mt * 16 + (lane >> 2);
            const int c0 = bcol + wn * 32 + nt * 8 + (lane & 3) * 2;
            float v0 = acc[mt][nt][0], v1 = acc[mt][nt][1];
            float v2 = acc[mt][nt][2], v3 = acc[mt][nt][3];
            if (bias) {
                float b0 = bias[c0], b1 = bias[c0 + 1];
                v0 += b0; v1 += b1; v2 += b0; v3 += b1;
            }
            const size_t o0 = (size_t)r0 * N + c0;
            const size_t o1 = (size_t)(r0 + 8) * N + c0;
            if (Cf) {
                *(float2*)&Cf[o0] = make_float2(v0, v1);
                *(float2*)&Cf[o1] = make_float2(v2, v3);
            }
            if (Chi) {
                __nv_bfloat16 h0 = __float2bfloat16(v0), h1 = __float2bfloat16(v1);
                __nv_bfloat16 h2 = __float2bfloat16(v2), h3 = __float2bfloat16(v3);
                *(uint32_t*)&Chi[o0] = pack_bf2(__bfloat162float(h0), __bfloat162float(h1));
                *(uint32_t*)&Chi[o1] = pack_bf2(__bfloat162float(h2), __bfloat162float(h3));
                *(uint32_t*)&Clo[o0] = pack_bf2(v0 - __bfloat162float(h0), v1 - __bfloat162float(h1));
                *(uint32_t*)&Clo[o1] = pack_bf2(v2 - __bfloat162float(h2), v3 - __bfloat162float(h3));
            }
        }
}

// ---------------------------------------------------------------------------
// conversion kernels
// ---------------------------------------------------------------------------
__global__ void split_f32(const float* __restrict__ in, __nv_bfloat16* __restrict__ hi,
                          __nv_bfloat16* __restrict__ lo, int n4)
{
    int i = blockIdx.x * blockDim.x + threadIdx.x;
    if (i >= n4) return;
    float4 v = ((const float4*)in)[i];
    __nv_bfloat16 h0 = __float2bfloat16(v.x), h1 = __float2bfloat16(v.y);
    __nv_bfloat16 h2 = __float2bfloat16(v.z), h3 = __float2bfloat16(v.w);
    ((uint2*)hi)[i] = make_uint2(pack_bf2(__bfloat162float(h0), __bfloat162float(h1)),
                                 pack_bf2(__bfloat162float(h2), __bfloat162float(h3)));
    ((uint2*)lo)[i] = make_uint2(pack_bf2(v.x - __bfloat162float(h0), v.y - __bfloat162float(h1)),
                                 pack_bf2(v.z - __bfloat162float(h2), v.w - __bfloat162float(h3)));
}

// in: [K, N] fp32 -> out hi/lo: [N, K] bf16 (transpose + split)
__global__ void transpose_split(const float* __restrict__ in,
                                __nv_bfloat16* __restrict__ hi,
                                __nv_bfloat16* __restrict__ lo, int K, int N)
{
    __shared__ float t[32][33];
    const int n0 = blockIdx.x * 32, k0 = blockIdx.y * 32;
    const int tx = threadIdx.x, ty = threadIdx.y;
#pragma unroll
    for (int i = 0; i < 32; i += 8)
        t[ty + i][tx] = in[(size_t)(k0 + ty + i) * N + n0 + tx];
    __syncthreads();
#pragma unroll
    for (int i = 0; i < 32; i += 8) {
        float v = t[tx][ty + i];
        __nv_bfloat16 h = __float2bfloat16(v);
        const size_t o = (size_t)(n0 + ty + i) * K + k0 + tx;
        hi[o] = h;
        lo[o] = __float2bfloat16(v - __bfloat162float(h));
    }
}

// bfused[n] = sum_k bg[k] * Gs[k,n] + bgs[n]
__global__ void bfused_kernel(const float* __restrict__ bg, const float* __restrict__ Gs,
                              const float* __restrict__ bgs, float* __restrict__ out,
                              int K, int N)
{
    int n = blockIdx.x * 128 + threadIdx.x;
    float acc = bgs[n];
    for (int k = 0; k < K; k++) acc = fmaf(bg[k], Gs[(size_t)k * N + n], acc);
    out[n] = acc;
}

// dec[b, col] = s_t_hat[b,:] @ Wdec[:, col] + bdec[col]
__global__ void dec_proj(const float* __restrict__ sth, const float* __restrict__ W,
                         const float* __restrict__ bias, float* __restrict__ out)
{
    __shared__ float s[1024];
    const int b = blockIdx.y;
    const int col = blockIdx.x * 128 + threadIdx.x;
    for (int k = threadIdx.x; k < 1024; k += 128) s[k] = sth[b * 1024 + k];
    __syncthreads();
    float acc = 0.0f;
    for (int k = 0; k < 1024; k++) acc = fmaf(s[k], W[(size_t)k * 1024 + col], acc);
    out[b * 1024 + col] = acc + bias[col];
}

// ---------------------------------------------------------------------------
// attention tail
// ---------------------------------------------------------------------------
__global__ void scores_kernel(const float* __restrict__ Wgstar,
                              const float* __restrict__ dec,
                              const float* __restrict__ cov,
                              const float* __restrict__ v,
                              float* __restrict__ scores, int T, int DH)
{
    const int bt = blockIdx.x;
    const int b = bt / T;
    const float c = cov[bt];
    const float4* w4 = (const float4*)(Wgstar + (size_t)bt * DH);
    const float4* d4 = (const float4*)(dec + (size_t)b * DH);
    const float4* v4 = (const float4*)v;

    float s = 0.0f;
    for (int i = threadIdx.x; i < DH / 4; i += 256) {
        float4 w = w4[i], dd = d4[i], vv = v4[i];
        s += tanh_fast(w.x + dd.x + c) * vv.x;
        s += tanh_fast(w.y + dd.y + c) * vv.y;
        s += tanh_fast(w.z + dd.z + c) * vv.z;
        s += tanh_fast(w.w + dd.w + c) * vv.w;
    }
#pragma unroll
    for (int o = 16; o > 0; o >>= 1) s += __shfl_xor_sync(0xffffffffu, s, o);
    __shared__ float red[8];
    if ((threadIdx.x & 31) == 0) red[threadIdx.x >> 5] = s;
    __syncthreads();
    if (threadIdx.x == 0) {
        float t = 0.0f;
#pragma unroll
        for (int i = 0; i < 8; i++) t += red[i];
        scores[bt] = t;
    }
}

__global__ void softmax_kernel(const float* __restrict__ scores,
                               const float* __restrict__ cov,
                               float* __restrict__ alpha,
                               float* __restrict__ out_cov,
                               float* __restrict__ out_alpha, int T)
{
    const int b = blockIdx.x;
    const int tid = threadIdx.x;
    __shared__ float red[256];
    float m = -1e30f;
    for (int t = tid; t < T; t += blockDim.x) m = fmaxf(m, scores[b * T + t]);
    red[tid] = m;
    __syncthreads();
    for (int off = 128; off > 0; off >>= 1) {
        if (tid < off) red[tid] = fmaxf(red[tid], red[tid + off]);
        __syncthreads();
    }
    m = red[0];
    __syncthreads();
    float s = 0.0f;
    for (int t = tid; t < T; t += blockDim.x) s += expf(scores[b * T + t] - m);
    red[tid] = s;
    __syncthreads();
    for (int off = 128; off > 0; off >>= 1) {
        if (tid < off) red[tid] += red[tid + off];
        __syncthreads();
    }
    s = red[0];
    const float inv = 1.0f / s;
    for (int t = tid; t < T; t += blockDim.x) {
        float a = expf(scores[b * T + t] - m) * inv;
        alpha[b * T + t] = a;
        out_alpha[b * T + t] = a;
        out_cov[b * T + t] = cov[b * T + t] + a;
    }
}

__global__ void context_kernel(const float* __restrict__ alpha,
                               const float* __restrict__ Gstar,
                               float* __restrict__ out_c, int T, int DH)
{
    const int b = blockIdx.x;
    __shared__ float a_s[512];
    for (int t = threadIdx.x; t < T; t += blockDim.x) a_s[t] = alpha[b * T + t];
    __syncthreads();
    const float* gbase = Gstar + (size_t)b * T * DH;
    for (int d = threadIdx.x; d < DH; d += blockDim.x) {
        float acc = 0.0f;
        for (int t = 0; t < T; t++)
            acc = fmaf(a_s[t], gbase[(size_t)t * DH + d], acc);
        out_c[(size_t)b * DH + d] = acc;
    }
}

// ---------------------------------------------------------------------------
extern "C" void kernel_launch(void* const* d_in, const int* in_sizes, int n_in,
                              void* d_out, int out_size)
{
    const float* gf   = (const float*)d_in[0];
    const float* sth  = (const float*)d_in[1];
    const float* cov  = (const float*)d_in[2];
    const float* Wg   = (const float*)d_in[3];
    const float* bg   = (const float*)d_in[4];
    const float* Gs   = (const float*)d_in[5];
    const float* bgs  = (const float*)d_in[6];
    const float* Wgs  = (const float*)d_in[7];
    const float* Wdec = (const float*)d_in[8];
    const float* bdec = (const float*)d_in[9];
    const float* v    = (const float*)d_in[10];

    const int GFD = in_sizes[4];        // 4096
    const int DH  = in_sizes[9];        // 1024
    const int b   = in_sizes[1] / DH;   // 32
    const int T   = in_sizes[2] / b;    // 196
    const int M   = b * T;              // 6272

    __nv_bfloat16 *gf_hi, *gf_lo, *Wg_hi, *Wg_lo, *GsT_hi, *GsT_lo;
    __nv_bfloat16 *WfT_hi, *WfT_lo, *WgsT_hi, *WgsT_lo, *Gstar_hi, *Gstar_lo;
    float *Gstar, *Wgstar, *bfused, *dec, *scores, *alpha;
    cudaGetSymbolAddress((void**)&gf_hi, g_gf_hi);
    cudaGetSymbolAddress((void**)&gf_lo, g_gf_lo);
    cudaGetSymbolAddress((void**)&Wg_hi, g_Wg_hi);
    cudaGetSymbolAddress((void**)&Wg_lo, g_Wg_lo);
    cudaGetSymbolAddress((void**)&GsT_hi, g_GsT_hi);
    cudaGetSymbolAddress((void**)&GsT_lo, g_GsT_lo);
    cudaGetSymbolAddress((void**)&WfT_hi, g_WfT_hi);
    cudaGetSymbolAddress((void**)&WfT_lo, g_WfT_lo);
    cudaGetSymbolAddress((void**)&WgsT_hi, g_WgsT_hi);
    cudaGetSymbolAddress((void**)&WgsT_lo, g_WgsT_lo);
    cudaGetSymbolAddress((void**)&Gstar, g_Gstar);
    cudaGetSymbolAddress((void**)&Gstar_hi, g_Gstar_hi);
    cudaGetSymbolAddress((void**)&Gstar_lo, g_Gstar_lo);
    cudaGetSymbolAddress((void**)&Wgstar, g_Wgstar);
    cudaGetSymbolAddress((void**)&bfused, g_bfused);
    cudaGetSymbolAddress((void**)&dec, g_dec);
    cudaGetSymbolAddress((void**)&scores, g_scores);
    cudaGetSymbolAddress((void**)&alpha, g_alpha);

    cudaFuncSetAttribute(tc_gemm, cudaFuncAttributeMaxDynamicSharedMemorySize, GEMM_SMEM);

    // operand prep
    split_f32<<<(M * GFD / 4 + 255) / 256, 256>>>(gf, gf_hi, gf_lo, M * GFD / 4);
    split_f32<<<(GFD * GFD / 4 + 255) / 256, 256>>>(Wg, Wg_hi, Wg_lo, GFD * GFD / 4);
    transpose_split<<<dim3(DH / 32, GFD / 32), dim3(32, 8)>>>(Gs, GsT_hi, GsT_lo, GFD, DH);
    transpose_split<<<dim3(DH / 32, DH / 32), dim3(32, 8)>>>(Wgs, WgsT_hi, WgsT_lo, DH, DH);
    bfused_kernel<<<DH / 128, 128>>>(bg, Gs, bgs, bfused, GFD, DH);

    // WfT[n,m] = sum_k Gs[k,n] * Wg[m,k]  (A = GsT [DH,GFD], B = Wg [GFD,GFD])
    tc_gemm<<<dim3(GFD / 128, DH / 128), 256, GEMM_SMEM>>>(
        GsT_hi, GsT_lo, Wg_hi, Wg_lo, nullptr, nullptr, WfT_hi, WfT_lo, DH, GFD, GFD);
    // g_star = gf @ Wf + bfused  (B = WfT [DH,GFD])
    tc_gemm<<<dim3(DH / 128, M / 128), 256, GEMM_SMEM>>>(
        gf_hi, gf_lo, WfT_hi, WfT_lo, bfused, Gstar, Gstar_hi, Gstar_lo, M, DH, GFD);
    // wgs = g_star @ Wgs  (B = WgsT [DH,DH])
    tc_gemm<<<dim3(DH / 128, M / 128), 256, GEMM_SMEM>>>(
        Gstar_hi, Gstar_lo, WgsT_hi, WgsT_lo, nullptr, Wgstar, nullptr, nullptr, M, DH, DH);

    dec_proj<<<dim3(DH / 128, b), 128>>>(sth, Wdec, bdec, dec);
    scores_kernel<<<M, 256>>>(Wgstar, dec, cov, v, scores, T, DH);

    float* out_c     = (float*)d_out;
    float* out_cov   = out_c + (size_t)b * DH;
    float* out_alpha = out_cov + (size_t)b * T;
    softmax_kernel<<<b, 256>>>(scores, cov, alpha, out_cov, out_alpha, T);
    context_kernel<<<b, 256>>>(alpha, Gstar, out_c, T, DH);
}

// round 6
// speedup vs baseline: 8.4507x; 1.2327x over previous
#include <cuda_runtime.h>
#include <cuda_bf16.h>
#include <cstdint>
#include <math.h>

// ---------------------------------------------------------------------------
// img_attention, mma.sync (HMMA) split-bf16 path, fused-weight algebra:
//   WfT    = (Wg @ Gs)^T            [1024, 4096]
//   bfused = bg @ Gs + bgs          [1024]
//   g_star = gf @ Wf + bfused       [M, 1024]
//   wgs    = g_star @ Wgs           [M, 1024]
//   dec    = s_t_hat @ Wdec + bdec  [32, 1024]
//   scores = tanh(wgs + dec + cov) @ v; alpha = softmax_T; c = alpha @ g_star
// Output: [c_img (b*DH) | coverage_new (b*T) | alpha (b*T)]
// ---------------------------------------------------------------------------

// ---- scratch (__device__ globals; allocation-free rule) ----
__device__ __align__(1024) __nv_bfloat16 g_gf_hi[25690112];
__device__ __align__(1024) __nv_bfloat16 g_gf_lo[25690112];
__device__ __align__(1024) __nv_bfloat16 g_Wg_hi[16777216];
__device__ __align__(1024) __nv_bfloat16 g_Wg_lo[16777216];
__device__ __align__(1024) __nv_bfloat16 g_GsT_hi[4194304];
__device__ __align__(1024) __nv_bfloat16 g_GsT_lo[4194304];
__device__ __align__(1024) __nv_bfloat16 g_WfT_hi[4194304];
__device__ __align__(1024) __nv_bfloat16 g_WfT_lo[4194304];
__device__ __align__(1024) __nv_bfloat16 g_WgsT_hi[1048576];
__device__ __align__(1024) __nv_bfloat16 g_WgsT_lo[1048576];
__device__ __align__(1024) float g_Gstar[6422528];
__device__ __align__(1024) __nv_bfloat16 g_Gstar_hi[6422528];
__device__ __align__(1024) __nv_bfloat16 g_Gstar_lo[6422528];
__device__ __align__(1024) float g_Wgstar[6422528];
__device__ __align__(1024) float g_bfused[1024];
__device__ __align__(1024) float g_dec[32768];
__device__ __align__(1024) float g_scores[6272];
__device__ __align__(1024) float g_alpha[6272];

// ---------------------------------------------------------------------------
// helpers
// ---------------------------------------------------------------------------
__device__ __forceinline__ uint32_t smem_u32(const void* p) {
    uint32_t a;
    asm("{ .reg .u64 t; cvta.to.shared.u64 t, %1; cvt.u32.u64 %0, t; }" : "=r"(a) : "l"(p));
    return a;
}
__device__ __forceinline__ void cp16(uint32_t s, const void* g) {
    asm volatile("cp.async.cg.shared.global [%0], [%1], 16;" :: "r"(s), "l"(g));
}
__device__ __forceinline__ void ldsm4(uint32_t* r, uint32_t a) {
    asm volatile("ldmatrix.sync.aligned.m8n8.x4.shared.b16 {%0,%1,%2,%3}, [%4];"
                 : "=r"(r[0]), "=r"(r[1]), "=r"(r[2]), "=r"(r[3]) : "r"(a));
}
__device__ __forceinline__ void mma16816(float* d, const uint32_t* a, const uint32_t* b) {
    asm volatile(
        "mma.sync.aligned.m16n8k16.row.col.f32.bf16.bf16.f32 "
        "{%0,%1,%2,%3}, {%4,%5,%6,%7}, {%8,%9}, {%0,%1,%2,%3};"
        : "+f"(d[0]), "+f"(d[1]), "+f"(d[2]), "+f"(d[3])
        : "r"(a[0]), "r"(a[1]), "r"(a[2]), "r"(a[3]), "r"(b[0]), "r"(b[1]));
}
__device__ __forceinline__ uint32_t pack_bf2(float x, float y) {
    __nv_bfloat162 h = __floats2bfloat162_rn(x, y);
    return *(uint32_t*)&h;
}

// MUFU-free tanh: tanh(x) = sign(x) * (1-u)/(1+u), u = exp(-2|x|).
// exp via exp2 poly (deg-5 FMA, rel err ~2.4e-6) + exponent splice;
// reciprocal of (1+u) in [1,2] via minimax-linear seed + 3 Newton (FMA only).
__device__ __forceinline__ float tanh_fma(float x) {
    float ax = fminf(fabsf(x), 9.0f);
    float y  = -2.88539008f * ax;                  // -2*log2(e)*|x|, in [-26, 0]
    float nf = rintf(y);
    float f  = y - nf;                             // [-0.5, 0.5]
    float p  = 1.33335581e-3f;
    p = fmaf(p, f, 9.61812910e-3f);
    p = fmaf(p, f, 5.55041087e-2f);
    p = fmaf(p, f, 2.40226507e-1f);
    p = fmaf(p, f, 6.93147181e-1f);
    p = fmaf(p, f, 1.0f);                          // 2^f
    int ni = (int)nf;
    float u = __int_as_float(__float_as_int(p) + (ni << 23));   // exp(-2|x|)
    float d = 1.0f + u;                            // [1, 2]
    float r = fmaf(-0.5f, d, 1.45711f);            // ~1/d seed, |rel err| < 0.09
    r = r * fmaf(-d, r, 2.0f);
    r = r * fmaf(-d, r, 2.0f);
    r = r * fmaf(-d, r, 2.0f);                     // 1/d to ~3e-9
    return copysignf((1.0f - u) * r, x);
}

// ---------------------------------------------------------------------------
// HMMA GEMM: C[M,N] = A[M,K] @ B^T (B stored [N,K]), split-bf16 3xMMA.
// BM=BN=128, BK=64, 3-stage cp.async, 8 warps (2m x 4n), warp tile 64x32.
// ---------------------------------------------------------------------------
#define BKT 64
#define OP_BYTES (128 * 64 * 2)          // 16 KB per operand tile
#define STG_BYTES (4 * OP_BYTES)         // 64 KB per stage
#define GEMM_SMEM (3 * STG_BYTES)        // 192 KB

__device__ __forceinline__ void load_stage(uint32_t stg,
    const __nv_bfloat16* __restrict__ Ah, const __nv_bfloat16* __restrict__ Al,
    const __nv_bfloat16* __restrict__ Bh, const __nv_bfloat16* __restrict__ Bl,
    int brow, int bcol, int K, int k0, int tid)
{
#pragma unroll
    for (int op = 0; op < 4; op++) {
        const __nv_bfloat16* P = (op == 0) ? Ah : (op == 1) ? Al : (op == 2) ? Bh : Bl;
        const int row0 = (op < 2) ? brow : bcol;
#pragma unroll
        for (int it = 0; it < 4; it++) {
            int idx = tid + it * 256;        // 0..1023
            int r = idx >> 3, c = idx & 7;
            uint32_t dst = stg + op * OP_BYTES + r * 128 + (((uint32_t)(c ^ (r & 7))) << 4);
            cp16(dst, P + (size_t)(row0 + r) * K + k0 + c * 8);
        }
    }
}

__global__ __launch_bounds__(256, 1)
void tc_gemm(const __nv_bfloat16* __restrict__ Ahi, const __nv_bfloat16* __restrict__ Alo,
             const __nv_bfloat16* __restrict__ Bhi, const __nv_bfloat16* __restrict__ Blo,
             const float* __restrict__ bias,
             float* __restrict__ Cf, __nv_bfloat16* __restrict__ Chi,
             __nv_bfloat16* __restrict__ Clo,
             int M, int N, int K)
{
    extern __shared__ __align__(128) char smem[];
    const uint32_t sbase = smem_u32(smem);
    const int tid = threadIdx.x, wid = tid >> 5, lane = tid & 31;
    const int wm = wid >> 2, wn = wid & 3;          // 2 x 4 warp grid
    const int brow = blockIdx.y * 128, bcol = blockIdx.x * 128;
    const int KT = K / BKT;

    const int rowA = wm * 64 + (lane & 15);
    const int phA  = rowA & 7;
    const int hiA  = lane >> 4;
    const int rowB = wn * 32 + ((lane >> 4) << 3) + (lane & 7);
    const int phB  = lane & 7;
    const int hiB  = (lane >> 3) & 1;

    float acc[4][4][4];
#pragma unroll
    for (int mt = 0; mt < 4; mt++)
#pragma unroll
        for (int nt = 0; nt < 4; nt++)
#pragma unroll
            for (int j = 0; j < 4; j++) acc[mt][nt][j] = 0.0f;

    load_stage(sbase, Ahi, Alo, Bhi, Blo, brow, bcol, K, 0, tid);
    asm volatile("cp.async.commit_group;" ::: "memory");
    if (KT > 1) {
        load_stage(sbase + STG_BYTES, Ahi, Alo, Bhi, Blo, brow, bcol, K, BKT, tid);
        asm volatile("cp.async.commit_group;" ::: "memory");
    }

    for (int kt = 0; kt < KT; kt++) {
        // pending groups here: tiles kt, kt+1. Drain tile kt before reading.
        if (kt + 1 < KT) asm volatile("cp.async.wait_group 1;" ::: "memory");
        else             asm volatile("cp.async.wait_group 0;" ::: "memory");
        __syncthreads();

        const uint32_t stg = sbase + (kt % 3) * STG_BYTES;
        const uint32_t aH = stg, aL = stg + OP_BYTES;
        const uint32_t bH = stg + 2 * OP_BYTES, bL = stg + 3 * OP_BYTES;

#pragma unroll
        for (int ks = 0; ks < 4; ks++) {
            uint32_t ah[4][4], al[4][4], bh[2][4], bl[2][4];
            const uint32_t cA = ((uint32_t)((ks * 2 + hiA) ^ phA)) << 4;
            const uint32_t cB = ((uint32_t)((ks * 2 + hiB) ^ phB)) << 4;
#pragma unroll
            for (int mt = 0; mt < 4; mt++) {
                uint32_t ro = (uint32_t)(rowA + mt * 16) * 128 + cA;
                ldsm4(ah[mt], aH + ro);
                ldsm4(al[mt], aL + ro);
            }
#pragma unroll
            for (int p = 0; p < 2; p++) {
                uint32_t ro = (uint32_t)(rowB + p * 16) * 128 + cB;
                ldsm4(bh[p], bH + ro);
                ldsm4(bl[p], bL + ro);
            }
#pragma unroll
            for (int mt = 0; mt < 4; mt++)
#pragma unroll
                for (int nt = 0; nt < 4; nt++) {
                    float* d = acc[mt][nt];
                    const uint32_t* bhf = &bh[nt >> 1][(nt & 1) * 2];
                    const uint32_t* blf = &bl[nt >> 1][(nt & 1) * 2];
                    mma16816(d, ah[mt], bhf);
                    mma16816(d, ah[mt], blf);
                    mma16816(d, al[mt], bhf);
                }
        }

        if (kt + 2 < KT) {
            load_stage(sbase + ((kt + 2) % 3) * STG_BYTES,
                       Ahi, Alo, Bhi, Blo, brow, bcol, K, (kt + 2) * BKT, tid);
            asm volatile("cp.async.commit_group;" ::: "memory");
        }
    }

#pragma unroll
    for (int mt = 0; mt < 4; mt++)
#pragma unroll
        for (int nt = 0; nt < 4; nt++) {
            const int r0 = brow + wm * 64 + mt * 16 + (lane >> 2);
            const int c0 = bcol + wn * 32 + nt * 8 + (lane & 3) * 2;
            float v0 = acc[mt][nt][0], v1 = acc[mt][nt][1];
            float v2 = acc[mt][nt][2], v3 = acc[mt][nt][3];
            if (bias) {
                float b0 = bias[c0], b1 = bias[c0 + 1];
                v0 += b0; v1 += b1; v2 += b0; v3 += b1;
            }
            const size_t o0 = (size_t)r0 * N + c0;
            const size_t o1 = (size_t)(r0 + 8) * N + c0;
            if (Cf) {
                *(float2*)&Cf[o0] = make_float2(v0, v1);
                *(float2*)&Cf[o1] = make_float2(v2, v3);
            }
            if (Chi) {
                __nv_bfloat16 h0 = __float2bfloat16(v0), h1 = __float2bfloat16(v1);
                __nv_bfloat16 h2 = __float2bfloat16(v2), h3 = __float2bfloat16(v3);
                *(uint32_t*)&Chi[o0] = pack_bf2(__bfloat162float(h0), __bfloat162float(h1));
                *(uint32_t*)&Chi[o1] = pack_bf2(__bfloat162float(h2), __bfloat162float(h3));
                *(uint32_t*)&Clo[o0] = pack_bf2(v0 - __bfloat162float(h0), v1 - __bfloat162float(h1));
                *(uint32_t*)&Clo[o1] = pack_bf2(v2 - __bfloat162float(h2), v3 - __bfloat162float(h3));
            }
        }
}

// ---------------------------------------------------------------------------
// conversion kernels
// ---------------------------------------------------------------------------
__global__ void split_f32(const float* __restrict__ in, __nv_bfloat16* __restrict__ hi,
                          __nv_bfloat16* __restrict__ lo, int n4)
{
    int i = blockIdx.x * blockDim.x + threadIdx.x;
    if (i >= n4) return;
    float4 v = ((const float4*)in)[i];
    __nv_bfloat16 h0 = __float2bfloat16(v.x), h1 = __float2bfloat16(v.y);
    __nv_bfloat16 h2 = __float2bfloat16(v.z), h3 = __float2bfloat16(v.w);
    ((uint2*)hi)[i] = make_uint2(pack_bf2(__bfloat162float(h0), __bfloat162float(h1)),
                                 pack_bf2(__bfloat162float(h2), __bfloat162float(h3)));
    ((uint2*)lo)[i] = make_uint2(pack_bf2(v.x - __bfloat162float(h0), v.y - __bfloat162float(h1)),
                                 pack_bf2(v.z - __bfloat162float(h2), v.w - __bfloat162float(h3)));
}

// in: [K, N] fp32 -> out hi/lo: [N, K] bf16 (transpose + split)
__global__ void transpose_split(const float* __restrict__ in,
                                __nv_bfloat16* __restrict__ hi,
                                __nv_bfloat16* __restrict__ lo, int K, int N)
{
    __shared__ float t[32][33];
    const int n0 = blockIdx.x * 32, k0 = blockIdx.y * 32;
    const int tx = threadIdx.x, ty = threadIdx.y;
#pragma unroll
    for (int i = 0; i < 32; i += 8)
        t[ty + i][tx] = in[(size_t)(k0 + ty + i) * N + n0 + tx];
    __syncthreads();
#pragma unroll
    for (int i = 0; i < 32; i += 8) {
        float v = t[tx][ty + i];
        __nv_bfloat16 h = __float2bfloat16(v);
        const size_t o = (size_t)(n0 + ty + i) * K + k0 + tx;
        hi[o] = h;
        lo[o] = __float2bfloat16(v - __bfloat162float(h));
    }
}

// bfused[n] = sum_k bg[k] * Gs[k,n] + bgs[n]
// 32 blocks; block = 32 cols x 8 k-groups; smem reduce over k-groups.
__global__ void bfused_kernel(const float* __restrict__ bg, const float* __restrict__ Gs,
                              const float* __restrict__ bgs, float* __restrict__ out,
                              int K, int N)
{
    __shared__ float red[8][32];
    const int c  = threadIdx.x & 31;
    const int kg = threadIdx.x >> 5;
    const int n  = blockIdx.x * 32 + c;
    const int kslice = K / 8;
    float acc = 0.0f;
    const float* p = Gs + (size_t)(kg * kslice) * N + n;
#pragma unroll 8
    for (int k = 0; k < kslice; k++)
        acc = fmaf(bg[kg * kslice + k], p[(size_t)k * N], acc);
    red[kg][c] = acc;
    __syncthreads();
    if (kg == 0) {
        float s = bgs[n];
#pragma unroll
        for (int i = 0; i < 8; i++) s += red[i][c];
        out[n] = s;
    }
}

// dec[b, col] = s_t_hat[b,:] @ Wdec[:, col] + bdec[col]
__global__ void dec_proj(const float* __restrict__ sth, const float* __restrict__ W,
                         const float* __restrict__ bias, float* __restrict__ out)
{
    __shared__ float s[1024];
    const int b = blockIdx.y;
    const int col = blockIdx.x * 128 + threadIdx.x;
    for (int k = threadIdx.x; k < 1024; k += 128) s[k] = sth[b * 1024 + k];
    __syncthreads();
    float acc = 0.0f;
#pragma unroll 16
    for (int k = 0; k < 1024; k++) acc = fmaf(s[k], W[(size_t)k * 1024 + col], acc);
    out[b * 1024 + col] = acc + bias[col];
}

// ---------------------------------------------------------------------------
// attention tail
// ---------------------------------------------------------------------------
__global__ void scores_kernel(const float* __restrict__ Wgstar,
                              const float* __restrict__ dec,
                              const float* __restrict__ cov,
                              const float* __restrict__ v,
                              float* __restrict__ scores, int T, int DH)
{
    const int bt = blockIdx.x;
    const int b = bt / T;
    const float c = cov[bt];
    const float4* w4 = (const float4*)(Wgstar + (size_t)bt * DH);
    const float4* d4 = (const float4*)(dec + (size_t)b * DH);
    const float4* v4 = (const float4*)v;

    float s = 0.0f;
    for (int i = threadIdx.x; i < DH / 4; i += 256) {
        float4 w = w4[i], dd = d4[i], vv = v4[i];
        s += tanh_fma(w.x + dd.x + c) * vv.x;
        s += tanh_fma(w.y + dd.y + c) * vv.y;
        s += tanh_fma(w.z + dd.z + c) * vv.z;
        s += tanh_fma(w.w + dd.w + c) * vv.w;
    }
#pragma unroll
    for (int o = 16; o > 0; o >>= 1) s += __shfl_xor_sync(0xffffffffu, s, o);
    __shared__ float red[8];
    if ((threadIdx.x & 31) == 0) red[threadIdx.x >> 5] = s;
    __syncthreads();
    if (threadIdx.x == 0) {
        float t = 0.0f;
#pragma unroll
        for (int i = 0; i < 8; i++) t += red[i];
        scores[bt] = t;
    }
}

__global__ void softmax_kernel(const float* __restrict__ scores,
                               const float* __restrict__ cov,
                               float* __restrict__ alpha,
                               float* __restrict__ out_cov,
                               float* __restrict__ out_alpha, int T)
{
    const int b = blockIdx.x;
    const int tid = threadIdx.x;
    __shared__ float red[256];
    float m = -1e30f;
    for (int t = tid; t < T; t += blockDim.x) m = fmaxf(m, scores[b * T + t]);
    red[tid] = m;
    __syncthreads();
    for (int off = 128; off > 0; off >>= 1) {
        if (tid < off) red[tid] = fmaxf(red[tid], red[tid + off]);
        __syncthreads();
    }
    m = red[0];
    __syncthreads();
    float s = 0.0f;
    for (int t = tid; t < T; t += blockDim.x) s += expf(scores[b * T + t] - m);
    red[tid] = s;
    __syncthreads();
    for (int off = 128; off > 0; off >>= 1) {
        if (tid < off) red[tid] += red[tid + off];
        __syncthreads();
    }
    s = red[0];
    const float inv = 1.0f / s;
    for (int t = tid; t < T; t += blockDim.x) {
        float a = expf(scores[b * T + t] - m) * inv;
        alpha[b * T + t] = a;
        out_alpha[b * T + t] = a;
        out_cov[b * T + t] = cov[b * T + t] + a;
    }
}

// c[b, d] = sum_t alpha[b,t] * g_star[b,t,d]; grid (b, DH/128), block 128
__global__ void context_kernel(const float* __restrict__ alpha,
                               const float* __restrict__ Gstar,
                               float* __restrict__ out_c, int T, int DH)
{
    const int b = blockIdx.x;
    const int d = blockIdx.y * 128 + threadIdx.x;
    __shared__ float a_s[256];
    for (int t = threadIdx.x; t < T; t += blockDim.x) a_s[t] = alpha[b * T + t];
    __syncthreads();
    const float* gbase = Gstar + (size_t)b * T * DH + d;
    float acc = 0.0f;
#pragma unroll 4
    for (int t = 0; t < T; t++)
        acc = fmaf(a_s[t], gbase[(size_t)t * DH], acc);
    out_c[(size_t)b * DH + d] = acc;
}

// ---------------------------------------------------------------------------
extern "C" void kernel_launch(void* const* d_in, const int* in_sizes, int n_in,
                              void* d_out, int out_size)
{
    const float* gf   = (const float*)d_in[0];
    const float* sth  = (const float*)d_in[1];
    const float* cov  = (const float*)d_in[2];
    const float* Wg   = (const float*)d_in[3];
    const float* bg   = (const float*)d_in[4];
    const float* Gs   = (const float*)d_in[5];
    const float* bgs  = (const float*)d_in[6];
    const float* Wgs  = (const float*)d_in[7];
    const float* Wdec = (const float*)d_in[8];
    const float* bdec = (const float*)d_in[9];
    const float* v    = (const float*)d_in[10];

    const int GFD = in_sizes[4];        // 4096
    const int DH  = in_sizes[9];        // 1024
    const int b   = in_sizes[1] / DH;   // 32
    const int T   = in_sizes[2] / b;    // 196
    const int M   = b * T;              // 6272

    __nv_bfloat16 *gf_hi, *gf_lo, *Wg_hi, *Wg_lo, *GsT_hi, *GsT_lo;
    __nv_bfloat16 *WfT_hi, *WfT_lo, *WgsT_hi, *WgsT_lo, *Gstar_hi, *Gstar_lo;
    float *Gstar, *Wgstar, *bfused, *dec, *scores, *alpha;
    cudaGetSymbolAddress((void**)&gf_hi, g_gf_hi);
    cudaGetSymbolAddress((void**)&gf_lo, g_gf_lo);
    cudaGetSymbolAddress((void**)&Wg_hi, g_Wg_hi);
    cudaGetSymbolAddress((void**)&Wg_lo, g_Wg_lo);
    cudaGetSymbolAddress((void**)&GsT_hi, g_GsT_hi);
    cudaGetSymbolAddress((void**)&GsT_lo, g_GsT_lo);
    cudaGetSymbolAddress((void**)&WfT_hi, g_WfT_hi);
    cudaGetSymbolAddress((void**)&WfT_lo, g_WfT_lo);
    cudaGetSymbolAddress((void**)&WgsT_hi, g_WgsT_hi);
    cudaGetSymbolAddress((void**)&WgsT_lo, g_WgsT_lo);
    cudaGetSymbolAddress((void**)&Gstar, g_Gstar);
    cudaGetSymbolAddress((void**)&Gstar_hi, g_Gstar_hi);
    cudaGetSymbolAddress((void**)&Gstar_lo, g_Gstar_lo);
    cudaGetSymbolAddress((void**)&Wgstar, g_Wgstar);
    cudaGetSymbolAddress((void**)&bfused, g_bfused);
    cudaGetSymbolAddress((void**)&dec, g_dec);
    cudaGetSymbolAddress((void**)&scores, g_scores);
    cudaGetSymbolAddress((void**)&alpha, g_alpha);

    cudaFuncSetAttribute(tc_gemm, cudaFuncAttributeMaxDynamicSharedMemorySize, GEMM_SMEM);

    // operand prep
    split_f32<<<(M * GFD / 4 + 255) / 256, 256>>>(gf, gf_hi, gf_lo, M * GFD / 4);
    split_f32<<<(GFD * GFD / 4 + 255) / 256, 256>>>(Wg, Wg_hi, Wg_lo, GFD * GFD / 4);
    transpose_split<<<dim3(DH / 32, GFD / 32), dim3(32, 8)>>>(Gs, GsT_hi, GsT_lo, GFD, DH);
    transpose_split<<<dim3(DH / 32, DH / 32), dim3(32, 8)>>>(Wgs, WgsT_hi, WgsT_lo, DH, DH);
    bfused_kernel<<<DH / 32, 256>>>(bg, Gs, bgs, bfused, GFD, DH);

    // WfT[n,m] = sum_k Gs[k,n] * Wg[m,k]  (A = GsT [DH,GFD], B = Wg [GFD,GFD])
    tc_gemm<<<dim3(GFD / 128, DH / 128), 256, GEMM_SMEM>>>(
        GsT_hi, GsT_lo, Wg_hi, Wg_lo, nullptr, nullptr, WfT_hi, WfT_lo, DH, GFD, GFD);
    // g_star = gf @ Wf + bfused  (B = WfT [DH,GFD])
    tc_gemm<<<dim3(DH / 128, M / 128), 256, GEMM_SMEM>>>(
        gf_hi, gf_lo, WfT_hi, WfT_lo, bfused, Gstar, Gstar_hi, Gstar_lo, M, DH, GFD);
    // wgs = g_star @ Wgs  (B = WgsT [DH,DH])
    tc_gemm<<<dim3(DH / 128, M / 128), 256, GEMM_SMEM>>>(
        Gstar_hi, Gstar_lo, WgsT_hi, WgsT_lo, nullptr, Wgstar, nullptr, nullptr, M, DH, DH);

    dec_proj<<<dim3(DH / 128, b), 128>>>(sth, Wdec, bdec, dec);
    scores_kernel<<<M, 256>>>(Wgstar, dec, cov, v, scores, T, DH);

    float* out_c     = (float*)d_out;
    float* out_cov   = out_c + (size_t)b * DH;
    float* out_alpha = out_cov + (size_t)b * T;
    softmax_kernel<<<b, 256>>>(scores, cov, alpha, out_cov, out_alpha, T);
    context_kernel<<<dim3(b, DH / 128), 128>>>(alpha, Gstar, out_c, T, DH);
}